// round 3
// baseline (speedup 1.0000x reference)
#include <cuda_runtime.h>

#define DEV __device__ __forceinline__

// ---------------- shared-memory weight layout (floats) ----------------
static constexpr int OFF_WSELF = 0;                       // 15*128
static constexpr int OFF_BSELF = OFF_WSELF + 15 * 128;    // 128
static constexpr int OFF_WDYN  = OFF_BSELF + 128;         // 128*64
static constexpr int OFF_BDYN  = OFF_WDYN + 128 * 64;     // 64
static constexpr int OFF_HWH   = OFF_BDYN + 64;           // 3*3*16
static constexpr int OFF_HA1   = OFF_HWH + 144;           // 48
static constexpr int OFF_HA2   = OFF_HA1 + 48;            // 48
static constexpr int OFF_HWO   = OFF_HA2 + 48;            // 48*64
static constexpr int OFF_HWA1  = OFF_HWO + 48 * 64;       // 48  (hWo @ hao1)
static constexpr int OFF_HWA2  = OFF_HWA1 + 48;           // 48  (hWo @ hao2)
static constexpr int OFF_CWH   = OFF_HWA2 + 48;
static constexpr int OFF_CA1   = OFF_CWH + 144;
static constexpr int OFF_CA2   = OFF_CA1 + 48;
static constexpr int OFF_CWO   = OFF_CA2 + 48;
static constexpr int OFF_CWA1  = OFF_CWO + 48 * 64;
static constexpr int OFF_CWA2  = OFF_CWA1 + 48;
static constexpr int OFF_LW1   = OFF_CWA2 + 48;           // 108*64
static constexpr int OFF_LB1   = OFF_LW1 + 108 * 64;      // 64
static constexpr int OFF_LW2   = OFF_LB1 + 64;            // 64*64
static constexpr int OFF_LB2   = OFF_LW2 + 64 * 64;       // 64
static constexpr int OFF_CMW1  = OFF_LB2 + 64;            // 269*64
static constexpr int OFF_CMB1  = OFF_CMW1 + 269 * 64;     // 64
static constexpr int OFF_CMW2  = OFF_CMB1 + 64;           // 64*64
static constexpr int OFF_CMB2  = OFF_CMW2 + 64 * 64;      // 64
static constexpr int SMEM_FLOATS = OFF_CMB2 + 64;         // 49696 floats = 198784 B

static constexpr int OBS_STRIDE = 2064;   // 6 * 344
static constexpr int CUR = 5 * 344;       // 1720

DEV float lrelu2(float z)  { return z > 0.f ? z : 0.01f * z; }  // leaky(leaky(.,0.1),0.1)
DEV float lrelu02(float z) { return z > 0.f ? z : 0.2f  * z; }
DEV float eluf(float z)    { return z > 0.f ? z : (__expf(z) - 1.f); }

DEV void cp4(float* dst, const float* __restrict__ src, int n4, int tid, int bd) {
    float4* d = reinterpret_cast<float4*>(dst);
    const float4* sp = reinterpret_cast<const float4*>(src);
    for (int i = tid; i < n4; i += bd) d[i] = sp[i];
}

// acc[64] += vbuf[0..K-1] (per-thread local buffer) * sW[K x 64] (smem, row-major)
template<int K>
DEV void gemv64(float (&acc)[64], const float* vbuf, const float* sW) {
    #pragma unroll 1
    for (int k = 0; k < K; k++) {
        float v = vbuf[k];
        const float4* w = reinterpret_cast<const float4*>(sW) + k * 16;
        #pragma unroll
        for (int j = 0; j < 16; j++) {
            float4 q = w[j];
            acc[4*j+0] = fmaf(v, q.x, acc[4*j+0]);
            acc[4*j+1] = fmaf(v, q.y, acc[4*j+1]);
            acc[4*j+2] = fmaf(v, q.z, acc[4*j+2]);
            acc[4*j+3] = fmaf(v, q.w, acc[4*j+3]);
        }
    }
}

// Star-GAT collapsed to a blended 48-vector: xb = wE*x2_ego + wOtot*x2_other.
// Final GAT output = elu(xb @ Wo) (done by caller).
template<int N>
DEV void gat_blend(const float* __restrict__ xin,       // nodes 1..N-1, stride 6, first 3 floats
                   float e0, float e1, float e2,        // ego node coords
                   const float* s, int WH, int A1, int A2, int WA1, int WA2,
                   float* xb)                           // out: 48 (local buffer)
{
    float x2e[48], x2o[48];
    #pragma unroll
    for (int h = 0; h < 3; h++) {
        const float* Wh = s + WH + h * 48;   // [3][16]
        const float* a1 = s + A1 + h * 16;
        const float* a2 = s + A2 + h * 16;
        float h0[16];
        float s1 = 0.f, s20 = 0.f;
        #pragma unroll
        for (int t = 0; t < 16; t++) {
            float hv = fmaf(e0, Wh[t], fmaf(e1, Wh[16 + t], e2 * Wh[32 + t]));
            h0[t] = hv;
            s1  = fmaf(a1[t], hv, s1);
            s20 = fmaf(a2[t], hv, s20);
        }
        // softmax over row 0 of the star graph (all N nodes); scores are tiny -> no max-shift needed
        float w0 = __expf(lrelu02(s1 + s20));
        float den = w0;
        float ws[16];
        #pragma unroll
        for (int t = 0; t < 16; t++) ws[t] = w0 * h0[t];
        #pragma unroll 1
        for (int m = 0; m < N - 1; m++) {
            const float* xp = xin + m * 6;
            float x0 = xp[0], x1 = xp[1], x2v = xp[2];
            float hm[16]; float s2 = 0.f;
            #pragma unroll
            for (int t = 0; t < 16; t++) {
                float hv = fmaf(x0, Wh[t], fmaf(x1, Wh[16 + t], x2v * Wh[32 + t]));
                hm[t] = hv;
                s2 = fmaf(a2[t], hv, s2);
            }
            float wm = __expf(lrelu02(s1 + s2));
            den += wm;
            #pragma unroll
            for (int t = 0; t < 16; t++) ws[t] = fmaf(wm, hm[t], ws[t]);
        }
        float inv = __fdividef(1.f, den);
        #pragma unroll
        for (int t = 0; t < 16; t++) {
            x2e[h * 16 + t] = eluf(ws[t] * inv);   // ego node layer-1 output (concat heads)
            x2o[h * 16 + t] = eluf(h0[t]);         // every non-ego node's (identical) layer-1 output
        }
    }
    // layer-2 attention scores via precomputed Wo@ao1 / Wo@ao2
    float d1e = 0.f, d2e = 0.f, d2o = 0.f;
    #pragma unroll
    for (int k = 0; k < 48; k++) {
        d1e = fmaf(x2e[k], s[WA1 + k], d1e);
        d2e = fmaf(x2e[k], s[WA2 + k], d2e);
        d2o = fmaf(x2o[k], s[WA2 + k], d2o);
    }
    float eee = lrelu02(d1e + d2e);
    float eeo = lrelu02(d1e + d2o);
    float we = __expf(eee);
    float wo = (float)(N - 1) * __expf(eeo);
    float inv = __fdividef(1.f, we + wo);
    we *= inv; wo *= inv;
    #pragma unroll
    for (int k = 0; k < 48; k++) xb[k] = fmaf(we, x2e[k], wo * x2o[k]);
}

__global__ void __launch_bounds__(256, 1) pred_kernel(
    const float* __restrict__ obs,
    const float* __restrict__ W_self, const float* __restrict__ b_self,
    const float* __restrict__ W_dyn,  const float* __restrict__ b_dyn,
    const float* __restrict__ hWh, const float* __restrict__ ha1, const float* __restrict__ ha2,
    const float* __restrict__ hWo, const float* __restrict__ hao1, const float* __restrict__ hao2,
    const float* __restrict__ cWh, const float* __restrict__ ca1v, const float* __restrict__ ca2v,
    const float* __restrict__ cWo, const float* __restrict__ cao1, const float* __restrict__ cao2,
    const float* __restrict__ lW1, const float* __restrict__ lb1,
    const float* __restrict__ lW2, const float* __restrict__ lb2,
    const float* __restrict__ cmW1, const float* __restrict__ cmb1,
    const float* __restrict__ cmW2, const float* __restrict__ cmb2,
    float* __restrict__ out, int B)
{
    extern __shared__ float s[];
    const int tid = threadIdx.x, bd = blockDim.x;

    cp4(s + OFF_WSELF, W_self, 15 * 128 / 4, tid, bd);
    cp4(s + OFF_BSELF, b_self, 128 / 4, tid, bd);
    cp4(s + OFF_WDYN,  W_dyn,  128 * 64 / 4, tid, bd);
    cp4(s + OFF_BDYN,  b_dyn,  64 / 4, tid, bd);
    cp4(s + OFF_HWH,   hWh,    144 / 4, tid, bd);
    cp4(s + OFF_HA1,   ha1,    48 / 4, tid, bd);
    cp4(s + OFF_HA2,   ha2,    48 / 4, tid, bd);
    cp4(s + OFF_HWO,   hWo,    48 * 64 / 4, tid, bd);
    cp4(s + OFF_CWH,   cWh,    144 / 4, tid, bd);
    cp4(s + OFF_CA1,   ca1v,   48 / 4, tid, bd);
    cp4(s + OFF_CA2,   ca2v,   48 / 4, tid, bd);
    cp4(s + OFF_CWO,   cWo,    48 * 64 / 4, tid, bd);
    cp4(s + OFF_LW1,   lW1,    108 * 64 / 4, tid, bd);
    cp4(s + OFF_LB1,   lb1,    64 / 4, tid, bd);
    cp4(s + OFF_LW2,   lW2,    64 * 64 / 4, tid, bd);
    cp4(s + OFF_LB2,   lb2,    64 / 4, tid, bd);
    cp4(s + OFF_CMW1,  cmW1,   269 * 64 / 4, tid, bd);
    cp4(s + OFF_CMB1,  cmb1,   64 / 4, tid, bd);
    cp4(s + OFF_CMW2,  cmW2,   64 * 64 / 4, tid, bd);
    cp4(s + OFF_CMB2,  cmb2,   64 / 4, tid, bd);

    // Precompute Wo@ao1 / Wo@ao2 for both GATs (48 values each)
    if (tid < 192) {
        int g = tid / 48;
        int r = tid - g * 48;
        const float* Wo = (g < 2) ? hWo : cWo;
        const float* ao = (g == 0) ? hao1 : (g == 1) ? hao2 : (g == 2) ? cao1 : cao2;
        int dst = (g == 0) ? OFF_HWA1 : (g == 1) ? OFF_HWA2 : (g == 2) ? OFF_CWA1 : OFF_CWA2;
        float sum = 0.f;
        #pragma unroll 1
        for (int j = 0; j < 64; j++) sum = fmaf(Wo[r * 64 + j], ao[j], sum);
        s[dst + r] = sum;
    }
    __syncthreads();

    int b = blockIdx.x * bd + tid;
    if (b >= B) return;
    const float* o = obs + (long long)b * OBS_STRIDE;

    // ----- ego history (steps 1..5, self_[0:3]) -----
    float eh[15];
    #pragma unroll
    for (int st = 0; st < 5; st++) {
        const float* p = o + (st + 1) * 344 + 234;
        eh[st * 3 + 0] = p[0];
        eh[st * 3 + 1] = p[1];
        eh[st * 3 + 2] = p[2];
    }
    float e0g = eh[12], e1g = eh[13], e2g = eh[14];  // current ego coords

    float acc[64];   // working accumulator
    float ca[64];    // comb-MLP hidden accumulator
    float buf[64];   // per-thread local-memory staging (dynamic-index reads)

    // ----- ego feature: leaky2(ehist@W_self + b_self) @ W_dyn + b_dyn -----
    #pragma unroll
    for (int j = 0; j < 64; j++) acc[j] = s[OFF_BDYN + j];
    #pragma unroll 1
    for (int k = 0; k < 128; k++) {
        float z = s[OFF_BSELF + k];
        #pragma unroll
        for (int i = 0; i < 15; i++) z = fmaf(eh[i], s[OFF_WSELF + i * 128 + k], z);
        z = lrelu2(z);
        const float4* w = reinterpret_cast<const float4*>(s + OFF_WDYN) + k * 16;
        #pragma unroll
        for (int j = 0; j < 16; j++) {
            float4 q = w[j];
            acc[4*j+0] = fmaf(z, q.x, acc[4*j+0]);
            acc[4*j+1] = fmaf(z, q.y, acc[4*j+1]);
            acc[4*j+2] = fmaf(z, q.z, acc[4*j+2]);
            acc[4*j+3] = fmaf(z, q.w, acc[4*j+3]);
        }
    }

    // comb hidden init + ego rows (0..63)
    #pragma unroll
    for (int j = 0; j < 64; j++) { buf[j] = acc[j]; ca[j] = s[OFF_CMB1 + j]; }
    gemv64<64>(ca, buf, s + OFF_CMW1 + 0 * 64);

    // ----- HDV GAT (rows 64..127) -----
    gat_blend<13>(o + CUR + 0, e0g, e1g, e2g, s, OFF_HWH, OFF_HA1, OFF_HA2, OFF_HWA1, OFF_HWA2, buf);
    #pragma unroll
    for (int j = 0; j < 64; j++) acc[j] = 0.f;
    gemv64<48>(acc, buf, s + OFF_HWO);
    #pragma unroll
    for (int j = 0; j < 64; j++) buf[j] = eluf(acc[j]);
    gemv64<64>(ca, buf, s + OFF_CMW1 + 64 * 64);

    // ----- CAV GAT (rows 128..191) -----
    gat_blend<9>(o + CUR + 72, e0g, e1g, e2g, s, OFF_CWH, OFF_CA1, OFF_CA2, OFF_CWA1, OFF_CWA2, buf);
    #pragma unroll
    for (int j = 0; j < 64; j++) acc[j] = 0.f;
    gemv64<48>(acc, buf, s + OFF_CWO);
    #pragma unroll
    for (int j = 0; j < 64; j++) buf[j] = eluf(acc[j]);
    gemv64<64>(ca, buf, s + OFF_CMW1 + 128 * 64);

    // ----- lane MLP (rows 192..255) -----
    #pragma unroll
    for (int j = 0; j < 64; j++) acc[j] = s[OFF_LB1 + j];
    {
        const float4* lp = reinterpret_cast<const float4*>(o + CUR + 120);
        #pragma unroll 1
        for (int k4 = 0; k4 < 27; k4++) {
            float4 v = lp[k4];
            const float4* w = reinterpret_cast<const float4*>(s + OFF_LW1) + k4 * 64;
            #pragma unroll
            for (int c = 0; c < 4; c++) {
                float vc = (c == 0) ? v.x : (c == 1) ? v.y : (c == 2) ? v.z : v.w;
                #pragma unroll
                for (int j = 0; j < 16; j++) {
                    float4 q = w[c * 16 + j];
                    acc[4*j+0] = fmaf(vc, q.x, acc[4*j+0]);
                    acc[4*j+1] = fmaf(vc, q.y, acc[4*j+1]);
                    acc[4*j+2] = fmaf(vc, q.z, acc[4*j+2]);
                    acc[4*j+3] = fmaf(vc, q.w, acc[4*j+3]);
                }
            }
        }
    }
    #pragma unroll
    for (int j = 0; j < 64; j++) buf[j] = fmaxf(acc[j], 0.f);
    #pragma unroll
    for (int j = 0; j < 64; j++) acc[j] = s[OFF_LB2 + j];
    gemv64<64>(acc, buf, s + OFF_LW2);
    #pragma unroll
    for (int j = 0; j < 64; j++) buf[j] = fmaxf(acc[j], 0.f);
    gemv64<64>(ca, buf, s + OFF_CMW1 + 192 * 64);

    // ----- road / gen / exe (rows 256..268) -----
    buf[0]  = o[CUR + 228]; buf[1]  = o[CUR + 229];   // bott
    buf[2]  = o[CUR + 247]; buf[3]  = o[CUR + 248];   // dist_bott
    buf[4]  = o[CUR + 230]; buf[5]  = o[CUR + 231];   // road_end
    buf[6]  = o[CUR + 249]; buf[7]  = o[CUR + 250];   // dist_end
    buf[8]  = o[CUR + 232]; buf[9]  = o[CUR + 233];   // target
    buf[10] = o[CUR + 253];                           // gen
    buf[11] = o[CUR + 251]; buf[12] = o[CUR + 252];   // exe
    gemv64<13>(ca, buf, s + OFF_CMW1 + 256 * 64);

    // ----- final layer: relu(relu(ca) @ cmW2 + cmb2) -----
    #pragma unroll
    for (int j = 0; j < 64; j++) buf[j] = fmaxf(ca[j], 0.f);
    #pragma unroll
    for (int j = 0; j < 64; j++) acc[j] = s[OFF_CMB2 + j];
    gemv64<64>(acc, buf, s + OFF_CMW2);

    float4* op = reinterpret_cast<float4*>(out + (long long)b * 64);
    #pragma unroll
    for (int j = 0; j < 16; j++) {
        float4 q;
        q.x = fmaxf(acc[4*j+0], 0.f);
        q.y = fmaxf(acc[4*j+1], 0.f);
        q.z = fmaxf(acc[4*j+2], 0.f);
        q.w = fmaxf(acc[4*j+3], 0.f);
        op[j] = q;
    }
}

extern "C" void kernel_launch(void* const* d_in, const int* in_sizes, int n_in,
                              void* d_out, int out_size) {
    const float* obs    = (const float*)d_in[0];
    const float* W_self = (const float*)d_in[1];
    const float* b_self = (const float*)d_in[2];
    const float* W_dyn  = (const float*)d_in[3];
    const float* b_dyn  = (const float*)d_in[4];
    const float* hWh    = (const float*)d_in[5];
    const float* ha1    = (const float*)d_in[6];
    const float* ha2    = (const float*)d_in[7];
    const float* hWo    = (const float*)d_in[8];
    const float* hao1   = (const float*)d_in[9];
    const float* hao2   = (const float*)d_in[10];
    const float* cWh    = (const float*)d_in[11];
    const float* ca1v   = (const float*)d_in[12];
    const float* ca2v   = (const float*)d_in[13];
    const float* cWo    = (const float*)d_in[14];
    const float* cao1   = (const float*)d_in[15];
    const float* cao2   = (const float*)d_in[16];
    const float* lW1    = (const float*)d_in[17];
    const float* lb1    = (const float*)d_in[18];
    const float* lW2    = (const float*)d_in[19];
    const float* lb2    = (const float*)d_in[20];
    const float* cmW1   = (const float*)d_in[21];
    const float* cmb1   = (const float*)d_in[22];
    const float* cmW2   = (const float*)d_in[23];
    const float* cmb2   = (const float*)d_in[24];

    int B = in_sizes[0] / OBS_STRIDE;
    size_t smem = (size_t)SMEM_FLOATS * sizeof(float);
    cudaFuncSetAttribute(pred_kernel, cudaFuncAttributeMaxDynamicSharedMemorySize, (int)smem);

    dim3 block(256);
    dim3 grid((B + 255) / 256);
    pred_kernel<<<grid, block, smem>>>(
        obs, W_self, b_self, W_dyn, b_dyn,
        hWh, ha1, ha2, hWo, hao1, hao2,
        cWh, ca1v, ca2v, cWo, cao1, cao2,
        lW1, lb1, lW2, lb2,
        cmW1, cmb1, cmW2, cmb2,
        (float*)d_out, B);
}

// round 5
// speedup vs baseline: 1.0741x; 1.0741x over previous
#include <cuda_runtime.h>

#define DEV __device__ __forceinline__

// ---------------- shared-memory weight layout (floats) ----------------
static constexpr int OFF_WSELF = 0;                       // 15*128
static constexpr int OFF_BSELF = OFF_WSELF + 15 * 128;    // 128
static constexpr int OFF_WDYN  = OFF_BSELF + 128;         // 128*64
static constexpr int OFF_BDYN  = OFF_WDYN + 128 * 64;     // 64
static constexpr int OFF_HWH   = OFF_BDYN + 64;           // 3*3*16
static constexpr int OFF_HA1   = OFF_HWH + 144;           // 48
static constexpr int OFF_HA2   = OFF_HA1 + 48;            // 48
static constexpr int OFF_HWO   = OFF_HA2 + 48;            // 48*64
static constexpr int OFF_HWA1  = OFF_HWO + 48 * 64;       // 48  (hWo @ hao1)
static constexpr int OFF_HWA2  = OFF_HWA1 + 48;           // 48  (hWo @ hao2)
static constexpr int OFF_CWH   = OFF_HWA2 + 48;
static constexpr int OFF_CA1   = OFF_CWH + 144;
static constexpr int OFF_CA2   = OFF_CA1 + 48;
static constexpr int OFF_CWO   = OFF_CA2 + 48;
static constexpr int OFF_CWA1  = OFF_CWO + 48 * 64;
static constexpr int OFF_CWA2  = OFF_CWA1 + 48;
static constexpr int OFF_LW1   = OFF_CWA2 + 48;           // 108*64
static constexpr int OFF_LB1   = OFF_LW1 + 108 * 64;      // 64
static constexpr int OFF_LW2   = OFF_LB1 + 64;            // 64*64
static constexpr int OFF_LB2   = OFF_LW2 + 64 * 64;       // 64
static constexpr int OFF_CMW1  = OFF_LB2 + 64;            // 269*64
static constexpr int OFF_CMB1  = OFF_CMW1 + 269 * 64;     // 64
static constexpr int OFF_CMW2  = OFF_CMB1 + 64;           // 64*64
static constexpr int OFF_CMB2  = OFF_CMW2 + 64 * 64;      // 64
static constexpr int SMEM_FLOATS = OFF_CMB2 + 64;         // 49696 floats = 198784 B

static constexpr int OBS_STRIDE = 2064;   // 6 * 344
static constexpr int CUR = 5 * 344;       // 1720

static constexpr int BLOCK = 224;
static constexpr int GRID  = 148;

DEV float lrelu2(float z)  { return z > 0.f ? z : 0.01f * z; }  // leaky(leaky(.,0.1),0.1)
DEV float lrelu02(float z) { return z > 0.f ? z : 0.2f  * z; }
DEV float eluf(float z)    { return z > 0.f ? z : (__expf(z) - 1.f); }

DEV void cp4(float* dst, const float* __restrict__ src, int n4, int tid, int bd) {
    float4* d = reinterpret_cast<float4*>(dst);
    const float4* sp = reinterpret_cast<const float4*>(src);
    for (int i = tid; i < n4; i += bd) d[i] = sp[i];
}

// acc[64] += v * row[0..63] (smem, 16B aligned). Fully unrolled (static acc idx).
DEV void gv64(float (&acc)[64], float v, const float* row) {
    const float4* w = reinterpret_cast<const float4*>(row);
    #pragma unroll
    for (int j = 0; j < 16; j++) {
        float4 q = w[j];
        acc[4*j+0] = fmaf(v, q.x, acc[4*j+0]);
        acc[4*j+1] = fmaf(v, q.y, acc[4*j+1]);
        acc[4*j+2] = fmaf(v, q.z, acc[4*j+2]);
        acc[4*j+3] = fmaf(v, q.w, acc[4*j+3]);
    }
}

// acc[64] += stage[0..K-1] (per-thread local memory) @ sW[K x 64] (smem rows).
DEV void gemv_stage(float (&acc)[64], volatile const float* st, const float* sW, int K) {
    #pragma unroll 1
    for (int k = 0; k < K; k++) {
        float v = st[k];
        gv64(acc, v, sW + k * 64);
    }
}

DEV void initAcc(float (&acc)[64], const float* bias) {
    const float4* bp = reinterpret_cast<const float4*>(bias);
    #pragma unroll
    for (int j = 0; j < 16; j++) {
        float4 q = bp[j];
        acc[4*j+0] = q.x; acc[4*j+1] = q.y; acc[4*j+2] = q.z; acc[4*j+3] = q.w;
    }
}

// Star-GAT collapsed: writes xb[48] = wE*x2_ego + wOtot*x2_other into x2e.
template<int N>
DEV void gat_blend(const float* __restrict__ xin,       // nodes 1..N-1, stride 6, first 3 floats
                   float e0, float e1, float e2,        // ego node coords
                   const float* s, int WH, int A1, int A2, int WA1, int WA2,
                   float (&x2e)[48])
{
    float x2o[48];
    #pragma unroll
    for (int h = 0; h < 3; h++) {
        const float* Wh = s + WH + h * 48;   // [3][16]
        const float* a1 = s + A1 + h * 16;
        const float* a2 = s + A2 + h * 16;
        float h0[16];
        float s1 = 0.f, s20 = 0.f;
        #pragma unroll
        for (int t = 0; t < 16; t++) {
            float hv = fmaf(e0, Wh[t], fmaf(e1, Wh[16 + t], e2 * Wh[32 + t]));
            h0[t] = hv;
            s1  = fmaf(a1[t], hv, s1);
            s20 = fmaf(a2[t], hv, s20);
        }
        float w0 = __expf(lrelu02(s1 + s20));
        float den = w0;
        float ws[16];
        #pragma unroll
        for (int t = 0; t < 16; t++) ws[t] = w0 * h0[t];
        #pragma unroll 1
        for (int m = 0; m < N - 1; m++) {
            const float* xp = xin + m * 6;
            float x0 = xp[0], x1 = xp[1], x2v = xp[2];
            float hm[16]; float s2 = 0.f;
            #pragma unroll
            for (int t = 0; t < 16; t++) {
                float hv = fmaf(x0, Wh[t], fmaf(x1, Wh[16 + t], x2v * Wh[32 + t]));
                hm[t] = hv;
                s2 = fmaf(a2[t], hv, s2);
            }
            float wm = __expf(lrelu02(s1 + s2));
            den += wm;
            #pragma unroll
            for (int t = 0; t < 16; t++) ws[t] = fmaf(wm, hm[t], ws[t]);
        }
        float inv = __fdividef(1.f, den);
        #pragma unroll
        for (int t = 0; t < 16; t++) {
            x2e[h * 16 + t] = eluf(ws[t] * inv);   // ego layer-1 output (concat heads)
            x2o[h * 16 + t] = eluf(h0[t]);         // identical layer-1 output of every non-ego node
        }
    }
    float d1e = 0.f, d2e = 0.f, d2o = 0.f;
    #pragma unroll
    for (int k = 0; k < 48; k++) {
        d1e = fmaf(x2e[k], s[WA1 + k], d1e);
        d2e = fmaf(x2e[k], s[WA2 + k], d2e);
        d2o = fmaf(x2o[k], s[WA2 + k], d2o);
    }
    float we = __expf(lrelu02(d1e + d2e));
    float wo = (float)(N - 1) * __expf(lrelu02(d1e + d2o));
    float inv = __fdividef(1.f, we + wo);
    we *= inv; wo *= inv;
    #pragma unroll
    for (int k = 0; k < 48; k++) x2e[k] = fmaf(we, x2e[k], wo * x2o[k]);  // x2o dies here
}

__global__ void __launch_bounds__(BLOCK, 1) pred_kernel(
    const float* __restrict__ obs,
    const float* __restrict__ W_self, const float* __restrict__ b_self,
    const float* __restrict__ W_dyn,  const float* __restrict__ b_dyn,
    const float* __restrict__ hWh, const float* __restrict__ ha1, const float* __restrict__ ha2,
    const float* __restrict__ hWo, const float* __restrict__ hao1, const float* __restrict__ hao2,
    const float* __restrict__ cWh, const float* __restrict__ ca1v, const float* __restrict__ ca2v,
    const float* __restrict__ cWo, const float* __restrict__ cao1, const float* __restrict__ cao2,
    const float* __restrict__ lW1, const float* __restrict__ lb1,
    const float* __restrict__ lW2, const float* __restrict__ lb2,
    const float* __restrict__ cmW1, const float* __restrict__ cmb1,
    const float* __restrict__ cmW2, const float* __restrict__ cmb2,
    float* __restrict__ out, int B)
{
    extern __shared__ float s[];
    const int tid = threadIdx.x, bd = blockDim.x;

    cp4(s + OFF_WSELF, W_self, 15 * 128 / 4, tid, bd);
    cp4(s + OFF_BSELF, b_self, 128 / 4, tid, bd);
    cp4(s + OFF_WDYN,  W_dyn,  128 * 64 / 4, tid, bd);
    cp4(s + OFF_BDYN,  b_dyn,  64 / 4, tid, bd);
    cp4(s + OFF_HWH,   hWh,    144 / 4, tid, bd);
    cp4(s + OFF_HA1,   ha1,    48 / 4, tid, bd);
    cp4(s + OFF_HA2,   ha2,    48 / 4, tid, bd);
    cp4(s + OFF_HWO,   hWo,    48 * 64 / 4, tid, bd);
    cp4(s + OFF_CWH,   cWh,    144 / 4, tid, bd);
    cp4(s + OFF_CA1,   ca1v,   48 / 4, tid, bd);
    cp4(s + OFF_CA2,   ca2v,   48 / 4, tid, bd);
    cp4(s + OFF_CWO,   cWo,    48 * 64 / 4, tid, bd);
    cp4(s + OFF_LW1,   lW1,    108 * 64 / 4, tid, bd);
    cp4(s + OFF_LB1,   lb1,    64 / 4, tid, bd);
    cp4(s + OFF_LW2,   lW2,    64 * 64 / 4, tid, bd);
    cp4(s + OFF_LB2,   lb2,    64 / 4, tid, bd);
    cp4(s + OFF_CMW1,  cmW1,   269 * 64 / 4, tid, bd);
    cp4(s + OFF_CMB1,  cmb1,   64 / 4, tid, bd);
    cp4(s + OFF_CMW2,  cmW2,   64 * 64 / 4, tid, bd);
    cp4(s + OFF_CMB2,  cmb2,   64 / 4, tid, bd);

    // Precompute Wo@ao1 / Wo@ao2 for both GATs (48 values each)
    if (tid < 192) {
        int g = tid / 48;
        int r = tid - g * 48;
        const float* Wo = (g < 2) ? hWo : cWo;
        const float* ao = (g == 0) ? hao1 : (g == 1) ? hao2 : (g == 2) ? cao1 : cao2;
        int dst = (g == 0) ? OFF_HWA1 : (g == 1) ? OFF_HWA2 : (g == 2) ? OFF_CWA1 : OFF_CWA2;
        float sum = 0.f;
        #pragma unroll 1
        for (int j = 0; j < 64; j++) sum = fmaf(Wo[r * 64 + j], ao[j], sum);
        s[dst + r] = sum;
    }
    __syncthreads();

    const int b = blockIdx.x * BLOCK + tid;
    if (b >= B) return;
    const float* o = obs + (long long)b * OBS_STRIDE;

    volatile float stage[64];   // per-thread local-memory staging for GEMV multipliers
    float ca[64];               // comb-MLP hidden accumulator (persists)
    float acc[64];              // working accumulator (reused)

    initAcc(ca, s + OFF_CMB1);

    const float e0g = o[CUR + 234], e1g = o[CUR + 235], e2g = o[CUR + 236];

    // ----- HDV GAT (comb rows 64..127) -----
    {
        float xb[48];
        gat_blend<13>(o + CUR + 0, e0g, e1g, e2g, s, OFF_HWH, OFF_HA1, OFF_HA2, OFF_HWA1, OFF_HWA2, xb);
        #pragma unroll
        for (int k = 0; k < 48; k++) stage[k] = xb[k];
    }
    initAcc(acc, s + OFF_BDYN);       // dummy init, overwritten below -- keep acc zeroed instead
    #pragma unroll
    for (int j = 0; j < 64; j++) acc[j] = 0.f;
    gemv_stage(acc, stage, s + OFF_HWO, 48);
    #pragma unroll
    for (int j = 0; j < 64; j++) stage[j] = eluf(acc[j]);
    gemv_stage(ca, stage, s + OFF_CMW1 + 64 * 64, 64);

    // ----- CAV GAT (comb rows 128..191) -----
    {
        float xb[48];
        gat_blend<9>(o + CUR + 72, e0g, e1g, e2g, s, OFF_CWH, OFF_CA1, OFF_CA2, OFF_CWA1, OFF_CWA2, xb);
        #pragma unroll
        for (int k = 0; k < 48; k++) stage[k] = xb[k];
    }
    #pragma unroll
    for (int j = 0; j < 64; j++) acc[j] = 0.f;
    gemv_stage(acc, stage, s + OFF_CWO, 48);
    #pragma unroll
    for (int j = 0; j < 64; j++) stage[j] = eluf(acc[j]);
    gemv_stage(ca, stage, s + OFF_CMW1 + 128 * 64, 64);

    // ----- ego feature (comb rows 0..63): leaky2(ehist@W_self+b_self)@W_dyn+b_dyn -----
    initAcc(acc, s + OFF_BDYN);
    {
        float eh[15];
        #pragma unroll
        for (int st = 0; st < 5; st++) {
            const float* p = o + (st + 1) * 344 + 234;
            eh[st * 3 + 0] = p[0];
            eh[st * 3 + 1] = p[1];
            eh[st * 3 + 2] = p[2];
        }
        #pragma unroll 1
        for (int k = 0; k < 128; k++) {
            float z = s[OFF_BSELF + k];
            #pragma unroll
            for (int i = 0; i < 15; i++) z = fmaf(eh[i], s[OFF_WSELF + i * 128 + k], z);
            gv64(acc, lrelu2(z), s + OFF_WDYN + k * 64);
        }
    }
    #pragma unroll
    for (int j = 0; j < 64; j++) stage[j] = acc[j];
    gemv_stage(ca, stage, s + OFF_CMW1 + 0 * 64, 64);

    // ----- lane MLP (comb rows 192..255) -----
    initAcc(acc, s + OFF_LB1);
    {
        const float4* lp = reinterpret_cast<const float4*>(o + CUR + 120);
        #pragma unroll 1
        for (int k4 = 0; k4 < 27; k4++) {
            float4 v = lp[k4];
            gv64(acc, v.x, s + OFF_LW1 + (4 * k4 + 0) * 64);
            gv64(acc, v.y, s + OFF_LW1 + (4 * k4 + 1) * 64);
            gv64(acc, v.z, s + OFF_LW1 + (4 * k4 + 2) * 64);
            gv64(acc, v.w, s + OFF_LW1 + (4 * k4 + 3) * 64);
        }
    }
    #pragma unroll
    for (int j = 0; j < 64; j++) stage[j] = fmaxf(acc[j], 0.f);
    initAcc(acc, s + OFF_LB2);
    gemv_stage(acc, stage, s + OFF_LW2, 64);
    #pragma unroll
    for (int j = 0; j < 64; j++) stage[j] = fmaxf(acc[j], 0.f);
    gemv_stage(ca, stage, s + OFF_CMW1 + 192 * 64, 64);

    // ----- road / gen / exe (comb rows 256..268) -----
    {
        stage[0]  = o[CUR + 228]; stage[1]  = o[CUR + 229];   // bott
        stage[2]  = o[CUR + 247]; stage[3]  = o[CUR + 248];   // dist_bott
        stage[4]  = o[CUR + 230]; stage[5]  = o[CUR + 231];   // road_end
        stage[6]  = o[CUR + 249]; stage[7]  = o[CUR + 250];   // dist_end
        stage[8]  = o[CUR + 232]; stage[9]  = o[CUR + 233];   // target
        stage[10] = o[CUR + 253];                             // gen
        stage[11] = o[CUR + 251]; stage[12] = o[CUR + 252];   // exe
        gemv_stage(ca, stage, s + OFF_CMW1 + 256 * 64, 13);
    }

    // ----- final layer: relu(relu(ca) @ cmW2 + cmb2) -----
    #pragma unroll
    for (int j = 0; j < 64; j++) stage[j] = fmaxf(ca[j], 0.f);
    initAcc(acc, s + OFF_CMB2);
    gemv_stage(acc, stage, s + OFF_CMW2, 64);

    float4* op = reinterpret_cast<float4*>(out + (long long)b * 64);
    #pragma unroll
    for (int j = 0; j < 16; j++) {
        float4 q;
        q.x = fmaxf(acc[4*j+0], 0.f);
        q.y = fmaxf(acc[4*j+1], 0.f);
        q.z = fmaxf(acc[4*j+2], 0.f);
        q.w = fmaxf(acc[4*j+3], 0.f);
        op[j] = q;
    }
}

extern "C" void kernel_launch(void* const* d_in, const int* in_sizes, int n_in,
                              void* d_out, int out_size) {
    const float* obs    = (const float*)d_in[0];
    const float* W_self = (const float*)d_in[1];
    const float* b_self = (const float*)d_in[2];
    const float* W_dyn  = (const float*)d_in[3];
    const float* b_dyn  = (const float*)d_in[4];
    const float* hWh    = (const float*)d_in[5];
    const float* ha1    = (const float*)d_in[6];
    const float* ha2    = (const float*)d_in[7];
    const float* hWo    = (const float*)d_in[8];
    const float* hao1   = (const float*)d_in[9];
    const float* hao2   = (const float*)d_in[10];
    const float* cWh    = (const float*)d_in[11];
    const float* ca1v   = (const float*)d_in[12];
    const float* ca2v   = (const float*)d_in[13];
    const float* cWo    = (const float*)d_in[14];
    const float* cao1   = (const float*)d_in[15];
    const float* cao2   = (const float*)d_in[16];
    const float* lW1    = (const float*)d_in[17];
    const float* lb1    = (const float*)d_in[18];
    const float* lW2    = (const float*)d_in[19];
    const float* lb2    = (const float*)d_in[20];
    const float* cmW1   = (const float*)d_in[21];
    const float* cmb1   = (const float*)d_in[22];
    const float* cmW2   = (const float*)d_in[23];
    const float* cmb2   = (const float*)d_in[24];

    int B = in_sizes[0] / OBS_STRIDE;
    size_t smem = (size_t)SMEM_FLOATS * sizeof(float);
    cudaFuncSetAttribute(pred_kernel, cudaFuncAttributeMaxDynamicSharedMemorySize, (int)smem);

    dim3 block(BLOCK);
    dim3 grid(GRID);
    pred_kernel<<<grid, block, smem>>>(
        obs, W_self, b_self, W_dyn, b_dyn,
        hWh, ha1, ha2, hWo, hao1, hao2,
        cWh, ca1v, ca2v, cWo, cao1, cao2,
        lW1, lb1, lW2, lb2,
        cmW1, cmb1, cmW2, cmb2,
        (float*)d_out, B);
}